// round 5
// baseline (speedup 1.0000x reference)
#include <cuda_runtime.h>
#include <cuda_bf16.h>

#define NU_  200000
#define NM_  80000
#define H_   128
#define FD_  512
#define EMAX_ 2000000

// ---------------- scratch (static __device__, aliased through dataflow) ----------------
// A: movie_x -> movie_r2 -> movie_o (in-place add)
// B: movie_p1 -> movie_ag
// C: movie_h
// D: movie_p2
// E: user_h
// F: user_r2 -> user_o (in-place add)
static __device__ float g_bufA[NM_*H_];
static __device__ float g_bufB[NM_*H_];
static __device__ float g_bufC[NM_*H_];
static __device__ float g_bufD[NM_*H_];
static __device__ float g_bufE[NU_*H_];
static __device__ float g_bufF[NU_*H_];

static __device__ int g_off_u[NU_+1];
static __device__ int g_off_m[NM_+1];
static __device__ int g_deg_u[NU_];
static __device__ int g_deg_m[NM_];
static __device__ int g_cur_u[NU_];
static __device__ int g_cur_m[NM_];
static __device__ int g_adj_u[EMAX_];   // per user: list of movie ids
static __device__ int g_adj_m[EMAX_];   // per movie: list of user ids
static __device__ float g_c1[H_];       // u0 @ Wl1_um
static __device__ float g_c2[H_];       // bl1_mu + u0 @ Wr1_mu

// ---------------- graph build ----------------
__global__ void k_zero()
{
    int i = blockIdx.x * blockDim.x + threadIdx.x;
    int stride = gridDim.x * blockDim.x;
    for (int j = i; j < NU_; j += stride) { g_deg_u[j] = 0; g_cur_u[j] = 0; }
    for (int j = i; j < NM_; j += stride) { g_deg_m[j] = 0; g_cur_m[j] = 0; }
}

__global__ void k_hist(const int* __restrict__ src, const int* __restrict__ dst, int E)
{
    int i = blockIdx.x * blockDim.x + threadIdx.x;
    int stride = gridDim.x * blockDim.x;
    for (int e = i; e < E; e += stride) {
        atomicAdd(&g_deg_u[src[e]], 1);
        atomicAdd(&g_deg_m[dst[e]], 1);
    }
}

// single-block exclusive scan
__global__ void __launch_bounds__(1024) k_scan(const int* __restrict__ deg, int* __restrict__ off, int n)
{
    __shared__ int ws[32];
    __shared__ int s_tot;
    int tid = threadIdx.x, lane = tid & 31, wid = tid >> 5;
    int carry = 0;
    for (int base = 0; base < n; base += 1024) {
        int i = base + tid;
        int v = (i < n) ? deg[i] : 0;
        int x = v;
        #pragma unroll
        for (int o = 1; o < 32; o <<= 1) {
            int y = __shfl_up_sync(0xffffffffu, x, o);
            if (lane >= o) x += y;
        }
        if (lane == 31) ws[wid] = x;
        __syncthreads();
        if (wid == 0) {
            int w = ws[lane];
            int xs = w;
            #pragma unroll
            for (int o = 1; o < 32; o <<= 1) {
                int y = __shfl_up_sync(0xffffffffu, xs, o);
                if (lane >= o) xs += y;
            }
            ws[lane] = xs - w;            // exclusive warp offset
            if (lane == 31) s_tot = xs;   // block total
        }
        __syncthreads();
        if (i < n) off[i] = carry + ws[wid] + (x - v);
        carry += s_tot;
        __syncthreads();
    }
    if (tid == 0) off[n] = carry;
}

__global__ void k_fill(const int* __restrict__ src, const int* __restrict__ dst, int E)
{
    int i = blockIdx.x * blockDim.x + threadIdx.x;
    int stride = gridDim.x * blockDim.x;
    for (int e = i; e < E; e += stride) {
        int s = src[e], d = dst[e];
        int pm = g_off_m[d] + atomicAdd(&g_cur_m[d], 1);
        g_adj_m[pm] = s;
        int pu = g_off_u[s] + atomicAdd(&g_cur_u[s], 1);
        g_adj_u[pu] = d;
    }
}

// ---------------- tiny precompute: c1 = u0@Wl1_um, c2 = bl1_mu + u0@Wr1_mu ----------------
__global__ void k_cvec(const float* __restrict__ u0,
                       const float* __restrict__ Wl1um,
                       const float* __restrict__ Wr1mu,
                       const float* __restrict__ bl1mu)
{
    int c = threadIdx.x;
    float s1 = 0.f, s2 = 0.f;
    #pragma unroll 8
    for (int k = 0; k < H_; k++) {
        float u = u0[k];
        s1 += u * Wl1um[k * H_ + c];
        s2 += u * Wr1mu[k * H_ + c];
    }
    g_c1[c] = s1;
    g_c2[c] = bl1mu[c] + s2;
}

// ---------------- fp32 GEMM: C[M,128] = A[M,K] @ W[K,128] (+ epilogue) ----------------
// mode 0: raw
// mode 1: + bias
// mode 2: relu( + bias + (deg[row]>0 ? cvec : 0) )
// mode 3: + bias + addM[row]   (addM may alias C, read-then-write per thread)
__global__ void __launch_bounds__(256) k_gemm(
    const float* __restrict__ A, const float* __restrict__ W,
    float* __restrict__ C, int M, int K, int mode,
    const float* __restrict__ bias, const float* __restrict__ cvec,
    const int* __restrict__ deg, const float* __restrict__ addM)
{
    __shared__ float As[64][32];
    __shared__ float Ws[32][128];
    int t = threadIdx.x;
    int rowBlock = blockIdx.x * 64;
    int c4 = (t & 31) * 4;
    int r0 = (t >> 5) * 8;

    float acc[8][4];
    #pragma unroll
    for (int i = 0; i < 8; i++)
        #pragma unroll
        for (int j = 0; j < 4; j++) acc[i][j] = 0.f;

    int nCh = K >> 5;
    for (int ch = 0; ch < nCh; ch++) {
        int k0 = ch * 32;
        // A tile: 64 rows x 32 k = 512 float4, 2 per thread
        #pragma unroll
        for (int p = 0; p < 2; p++) {
            int id = t + p * 256;
            int ar = id >> 3, aq = id & 7;
            int grow = rowBlock + ar;
            float4 v = make_float4(0.f, 0.f, 0.f, 0.f);
            if (grow < M) v = *(const float4*)&A[(size_t)grow * K + k0 + aq * 4];
            *(float4*)&As[ar][aq * 4] = v;
        }
        // W tile: 32 rows x 128 cols = 1024 float4, 4 per thread
        #pragma unroll
        for (int p = 0; p < 4; p++) {
            int id = t + p * 256;
            int wr = id >> 5, wc = (id & 31) * 4;
            *(float4*)&Ws[wr][wc] = *(const float4*)&W[(size_t)(k0 + wr) * 128 + wc];
        }
        __syncthreads();
        #pragma unroll
        for (int kk = 0; kk < 32; kk++) {
            float4 w = *(float4*)&Ws[kk][c4];
            #pragma unroll
            for (int i = 0; i < 8; i++) {
                float a = As[r0 + i][kk];
                acc[i][0] += a * w.x;
                acc[i][1] += a * w.y;
                acc[i][2] += a * w.z;
                acc[i][3] += a * w.w;
            }
        }
        __syncthreads();
    }

    float4 b4 = make_float4(0.f, 0.f, 0.f, 0.f);
    float4 cv = make_float4(0.f, 0.f, 0.f, 0.f);
    if (mode == 1 || mode == 2 || mode == 3) b4 = *(const float4*)&bias[c4];
    if (mode == 2) cv = *(const float4*)&cvec[c4];

    #pragma unroll
    for (int i = 0; i < 8; i++) {
        int grow = rowBlock + r0 + i;
        if (grow >= M) continue;
        float4 o = make_float4(acc[i][0], acc[i][1], acc[i][2], acc[i][3]);
        if (mode == 1) {
            o.x += b4.x; o.y += b4.y; o.z += b4.z; o.w += b4.w;
        } else if (mode == 2) {
            float ind = (deg[grow] > 0) ? 1.f : 0.f;
            o.x = fmaxf(o.x + b4.x + ind * cv.x, 0.f);
            o.y = fmaxf(o.y + b4.y + ind * cv.y, 0.f);
            o.z = fmaxf(o.z + b4.z + ind * cv.z, 0.f);
            o.w = fmaxf(o.w + b4.w + ind * cv.w, 0.f);
        } else if (mode == 3) {
            float4 a2 = *(const float4*)&addM[(size_t)grow * 128 + c4];
            o.x += b4.x + a2.x; o.y += b4.y + a2.y;
            o.z += b4.z + a2.z; o.w += b4.w + a2.w;
        }
        *(float4*)&C[(size_t)grow * 128 + c4] = o;
    }
}

// ---------------- mean aggregation over CSR, warp per node, lane owns 4 channels ----------------
// mode 0: out = relu(mean + cvec)
// mode 1: out = mean
// mode 2: out = mean + bias + addM[row]   (addM may alias out)
__global__ void __launch_bounds__(256) k_agg(
    const int* __restrict__ off, const int* __restrict__ adj,
    const float* __restrict__ X, float* __restrict__ out, int n, int mode,
    const float* __restrict__ cvec, const float* __restrict__ bias,
    const float* __restrict__ addM)
{
    int node = blockIdx.x * 8 + (threadIdx.x >> 5);
    int lane = threadIdx.x & 31;
    if (node >= n) return;
    int s = off[node], e = off[node + 1];
    float4 a0 = make_float4(0.f, 0.f, 0.f, 0.f);
    float4 a1 = make_float4(0.f, 0.f, 0.f, 0.f);
    int p = s;
    for (; p + 1 < e; p += 2) {
        int m0 = __ldg(&adj[p]);
        int m1 = __ldg(&adj[p + 1]);
        float4 v0 = *(const float4*)&X[(size_t)m0 * 128 + lane * 4];
        float4 v1 = *(const float4*)&X[(size_t)m1 * 128 + lane * 4];
        a0.x += v0.x; a0.y += v0.y; a0.z += v0.z; a0.w += v0.w;
        a1.x += v1.x; a1.y += v1.y; a1.z += v1.z; a1.w += v1.w;
    }
    if (p < e) {
        int m0 = __ldg(&adj[p]);
        float4 v0 = *(const float4*)&X[(size_t)m0 * 128 + lane * 4];
        a0.x += v0.x; a0.y += v0.y; a0.z += v0.z; a0.w += v0.w;
    }
    float4 acc = make_float4(a0.x + a1.x, a0.y + a1.y, a0.z + a1.z, a0.w + a1.w);
    float inv = (e > s) ? 1.f / (float)(e - s) : 0.f;
    acc.x *= inv; acc.y *= inv; acc.z *= inv; acc.w *= inv;

    float4 o = acc;
    if (mode == 0) {
        float4 c = *(const float4*)&cvec[lane * 4];
        o.x = fmaxf(acc.x + c.x, 0.f);
        o.y = fmaxf(acc.y + c.y, 0.f);
        o.z = fmaxf(acc.z + c.z, 0.f);
        o.w = fmaxf(acc.w + c.w, 0.f);
    } else if (mode == 2) {
        float4 b = *(const float4*)&bias[lane * 4];
        float4 a2 = *(const float4*)&addM[(size_t)node * 128 + lane * 4];
        o.x = acc.x + b.x + a2.x;
        o.y = acc.y + b.y + a2.y;
        o.z = acc.z + b.z + a2.z;
        o.w = acc.w + b.w + a2.w;
    }
    *(float4*)&out[(size_t)node * 128 + lane * 4] = o;
}

// ---------------- final edge dot: out[e] = <user_o[lu[e]], movie_o[lm[e]]> ----------------
__global__ void __launch_bounds__(256) k_dot(
    const int* __restrict__ lu, const int* __restrict__ lm,
    const float* __restrict__ U, const float* __restrict__ Mo,
    float* __restrict__ out, int n)
{
    int e = blockIdx.x * 8 + (threadIdx.x >> 5);
    int lane = threadIdx.x & 31;
    if (e >= n) return;
    int u = lu[e], m = lm[e];
    float4 a = *(const float4*)&U [(size_t)u * 128 + lane * 4];
    float4 b = *(const float4*)&Mo[(size_t)m * 128 + lane * 4];
    float p = a.x * b.x + a.y * b.y + a.z * b.z + a.w * b.w;
    #pragma unroll
    for (int o = 16; o > 0; o >>= 1) p += __shfl_xor_sync(0xffffffffu, p, o);
    if (lane == 0) out[e] = p;
}

// ---------------- launch ----------------
extern "C" void kernel_launch(void* const* d_in, const int* in_sizes, int n_in,
                              void* d_out, int out_size)
{
    const float* movie_feats = (const float*)d_in[0];
    const float* user_init   = (const float*)d_in[1];
    const int*   edge_src    = (const int*)d_in[2];
    const int*   edge_dst    = (const int*)d_in[3];
    const int*   lbl_user    = (const int*)d_in[4];
    const int*   lbl_movie   = (const int*)d_in[5];
    const float* Wm     = (const float*)d_in[7];
    const float* bm     = (const float*)d_in[8];
    const float* Wl1_um = (const float*)d_in[9];
    const float* bl1_um = (const float*)d_in[10];
    const float* Wr1_um = (const float*)d_in[11];
    const float* Wl1_mu = (const float*)d_in[12];
    const float* bl1_mu = (const float*)d_in[13];
    const float* Wr1_mu = (const float*)d_in[14];
    const float* Wl2_um = (const float*)d_in[15];
    const float* bl2_um = (const float*)d_in[16];
    const float* Wr2_um = (const float*)d_in[17];
    const float* Wl2_mu = (const float*)d_in[18];
    const float* bl2_mu = (const float*)d_in[19];
    const float* Wr2_mu = (const float*)d_in[20];

    int E  = in_sizes[2]; if (E > EMAX_) E = EMAX_;
    int EL = in_sizes[4];
    float* out = (float*)d_out;

    float *bufA, *bufB, *bufC, *bufD, *bufE, *bufF, *c1, *c2;
    int *off_u, *off_m, *deg_u, *deg_m, *adj_u, *adj_m;
    cudaGetSymbolAddress((void**)&bufA, g_bufA);
    cudaGetSymbolAddress((void**)&bufB, g_bufB);
    cudaGetSymbolAddress((void**)&bufC, g_bufC);
    cudaGetSymbolAddress((void**)&bufD, g_bufD);
    cudaGetSymbolAddress((void**)&bufE, g_bufE);
    cudaGetSymbolAddress((void**)&bufF, g_bufF);
    cudaGetSymbolAddress((void**)&c1,   g_c1);
    cudaGetSymbolAddress((void**)&c2,   g_c2);
    cudaGetSymbolAddress((void**)&off_u, g_off_u);
    cudaGetSymbolAddress((void**)&off_m, g_off_m);
    cudaGetSymbolAddress((void**)&deg_u, g_deg_u);
    cudaGetSymbolAddress((void**)&deg_m, g_deg_m);
    cudaGetSymbolAddress((void**)&adj_u, g_adj_u);
    cudaGetSymbolAddress((void**)&adj_m, g_adj_m);

    // ---- CSR build ----
    k_zero<<<782, 256>>>();
    k_hist<<<(E + 255) / 256, 256>>>(edge_src, edge_dst, E);
    k_scan<<<1, 1024>>>(deg_u, off_u, NU_);
    k_scan<<<1, 1024>>>(deg_m, off_m, NM_);
    k_fill<<<(E + 255) / 256, 256>>>(edge_src, edge_dst, E);

    // ---- constants from user_init ----
    k_cvec<<<1, H_>>>(user_init, Wl1_um, Wr1_mu, bl1_mu);

    int gM = (NM_ + 63) / 64;
    int gU = (NU_ + 63) / 64;

    // A: movie_x = movie_feats @ Wm + bm
    k_gemm<<<gM, 256>>>(movie_feats, Wm, bufA, NM_, FD_, 1, bm, nullptr, nullptr, nullptr);
    // C: movie_h = relu(movie_x @ Wr1_um + bl1_um + ind*c1)
    k_gemm<<<gM, 256>>>(bufA, Wr1_um, bufC, NM_, H_, 2, bl1_um, c1, deg_m, nullptr);
    // B: movie_p1 = movie_x @ Wl1_mu
    k_gemm<<<gM, 256>>>(bufA, Wl1_mu, bufB, NM_, H_, 0, nullptr, nullptr, nullptr, nullptr);
    // E: user_h = relu(mean_agg_u(movie_p1) + c2)
    k_agg<<<(NU_ + 7) / 8, 256>>>(off_u, adj_u, bufB, bufE, NU_, 0, c2, nullptr, nullptr);
    // A: movie_r2 = movie_h @ Wr2_um   (movie_x dead, reuse A)
    k_gemm<<<gM, 256>>>(bufC, Wr2_um, bufA, NM_, H_, 0, nullptr, nullptr, nullptr, nullptr);
    // D: movie_p2 = movie_h @ Wl2_mu
    k_gemm<<<gM, 256>>>(bufC, Wl2_mu, bufD, NM_, H_, 0, nullptr, nullptr, nullptr, nullptr);
    // B: movie_ag = mean_agg_m(user_h)   (movie_p1 dead, reuse B)
    k_agg<<<(NM_ + 7) / 8, 256>>>(off_m, adj_m, bufE, bufB, NM_, 1, nullptr, nullptr, nullptr);
    // A: movie_o = movie_ag @ Wl2_um + bl2_um + movie_r2   (in-place add into A)
    k_gemm<<<gM, 256>>>(bufB, Wl2_um, bufA, NM_, H_, 3, bl2_um, nullptr, nullptr, bufA);
    // F: user_r2 = user_h @ Wr2_mu
    k_gemm<<<gU, 256>>>(bufE, Wr2_mu, bufF, NU_, H_, 0, nullptr, nullptr, nullptr, nullptr);
    // F: user_o = mean_agg_u(movie_p2) + bl2_mu + user_r2   (in-place into F)
    k_agg<<<(NU_ + 7) / 8, 256>>>(off_u, adj_u, bufD, bufF, NU_, 2, nullptr, bl2_mu, bufF);
    // out[e] = <user_o[lu], movie_o[lm]>
    k_dot<<<(EL + 7) / 8, 256>>>(lbl_user, lbl_movie, bufF, bufA, out, EL);
}